// round 3
// baseline (speedup 1.0000x reference)
#include <cuda_runtime.h>
#include <cuda_bf16.h>
#include <cstdint>

// 2-layer LSTM (H=32) + LayerNorm. B=4096, T=512, D=6.
// Round 3: BPW=7 batches/warp, 4 warps/CTA (1 warp per SMSP), weights in
// shared with f32x2 k-pair layout; x staged through shared via cp.async in
// 16-step double-buffered chunks. FMA-pipe-bound by design.

#define T_STEPS 512
#define BATCH 4096
#define BPW 7
#define WARPS_PER_CTA 4
#define CTA_THREADS 128
#define NUM_CTAS 147
#define CHUNK 16
#define NCHUNK (T_STEPS / CHUNK)

// smem floats: weights 768 + 12288 = 13056 ; hbuf 4*448 ; xbuf 4*2*672
#define SMEM_FLOATS (13056 + 4*448 + 4*2*672)
#define SMEM_BYTES (SMEM_FLOATS * 4)

__device__ __forceinline__ unsigned long long pk2(float lo, float hi) {
    unsigned long long r;
    asm("mov.b64 %0, {%1,%2};" : "=l"(r)
        : "r"(__float_as_uint(lo)), "r"(__float_as_uint(hi)));
    return r;
}
__device__ __forceinline__ float2 upk2(unsigned long long v) {
    unsigned int lo, hi;
    asm("mov.b64 {%0,%1}, %2;" : "=r"(lo), "=r"(hi) : "l"(v));
    return make_float2(__uint_as_float(lo), __uint_as_float(hi));
}
__device__ __forceinline__ unsigned long long ffma2(
    unsigned long long a, unsigned long long b, unsigned long long c) {
    unsigned long long d;
    asm("fma.rn.f32x2 %0, %1, %2, %3;" : "=l"(d) : "l"(a), "l"(b), "l"(c));
    return d;
}
__device__ __forceinline__ float sigf(float x) {
    return __fdividef(1.0f, 1.0f + __expf(-x));
}
__device__ __forceinline__ float tanh_(float x) {
    return __fdividef(2.0f, 1.0f + __expf(-2.0f * x)) - 1.0f;
}
__device__ __forceinline__ void cp_async16(uint32_t s, const void* g) {
    asm volatile("cp.async.ca.shared.global [%0], [%1], 16;" :: "r"(s), "l"(g));
}

__global__ __launch_bounds__(CTA_THREADS, 1)
void lstm_enc_kernel(const float* __restrict__ x,
                     const float* __restrict__ W_ih0,
                     const float* __restrict__ W_hh0,
                     const float* __restrict__ b_ih0,
                     const float* __restrict__ b_hh0,
                     const float* __restrict__ W_ih1,
                     const float* __restrict__ W_hh1,
                     const float* __restrict__ b_ih1,
                     const float* __restrict__ b_hh1,
                     const float* __restrict__ ln_gamma,
                     const float* __restrict__ ln_beta,
                     float* __restrict__ out)
{
    extern __shared__ float smem[];
    float* sIh0if = smem;                 // [3kp][32j][4]
    float* sIh0go = sIh0if + 384;
    float* sHh0if = sIh0go + 384;         // [16kp][32j][4]
    float* sHh0go = sHh0if + 2048;
    float* sIh1if = sHh0go + 2048;
    float* sIh1go = sIh1if + 2048;
    float* sHh1if = sIh1go + 2048;
    float* sHh1go = sHh1if + 2048;
    float* hbuf   = sHh1go + 2048;        // 4 warps * 448
    float* xbuf   = hbuf + 4*448;         // 4 warps * 2 * 672

    const int tid = threadIdx.x;

    // ---- stage weights (k-pair layout): entry (kp*32+j)*4 =
    //  {W[g0*32+j][2kp], W[g0*32+j][2kp+1], W[g1*32+j][2kp], W[g1*32+j][2kp+1]}
    for (int i = tid; i < 512; i += CTA_THREADS) {
        int kp = i >> 5, j = i & 31;
        int k0 = 2 * kp, k1 = k0 + 1;
        ((float4*)sHh0if)[i] = make_float4(W_hh0[(j)*32+k0],    W_hh0[(j)*32+k1],
                                           W_hh0[(32+j)*32+k0], W_hh0[(32+j)*32+k1]);
        ((float4*)sHh0go)[i] = make_float4(W_hh0[(64+j)*32+k0], W_hh0[(64+j)*32+k1],
                                           W_hh0[(96+j)*32+k0], W_hh0[(96+j)*32+k1]);
        ((float4*)sIh1if)[i] = make_float4(W_ih1[(j)*32+k0],    W_ih1[(j)*32+k1],
                                           W_ih1[(32+j)*32+k0], W_ih1[(32+j)*32+k1]);
        ((float4*)sIh1go)[i] = make_float4(W_ih1[(64+j)*32+k0], W_ih1[(64+j)*32+k1],
                                           W_ih1[(96+j)*32+k0], W_ih1[(96+j)*32+k1]);
        ((float4*)sHh1if)[i] = make_float4(W_hh1[(j)*32+k0],    W_hh1[(j)*32+k1],
                                           W_hh1[(32+j)*32+k0], W_hh1[(32+j)*32+k1]);
        ((float4*)sHh1go)[i] = make_float4(W_hh1[(64+j)*32+k0], W_hh1[(64+j)*32+k1],
                                           W_hh1[(96+j)*32+k0], W_hh1[(96+j)*32+k1]);
    }
    for (int i = tid; i < 96; i += CTA_THREADS) {
        int kp = i >> 5, j = i & 31;
        int k0 = 2 * kp, k1 = k0 + 1;
        ((float4*)sIh0if)[i] = make_float4(W_ih0[(j)*6+k0],    W_ih0[(j)*6+k1],
                                           W_ih0[(32+j)*6+k0], W_ih0[(32+j)*6+k1]);
        ((float4*)sIh0go)[i] = make_float4(W_ih0[(64+j)*6+k0], W_ih0[(64+j)*6+k1],
                                           W_ih0[(96+j)*6+k0], W_ih0[(96+j)*6+k1]);
    }
    __syncthreads();

    const int wid = tid >> 5;
    const int j = tid & 31;
    const int task = blockIdx.x * WARPS_PER_CTA + wid;
    if (task * BPW >= BATCH) return;
    const int b0 = task * BPW;

    float* h0p = hbuf + wid * 448;              // [7][32]
    float* h1p = h0p + 224;                     // [7][32]
    float* xs  = xbuf + wid * 1344;             // 2 x [7][96]

    #pragma unroll
    for (int q = 0; q < BPW; q++) { h0p[q*32 + j] = 0.0f; h1p[q*32 + j] = 0.0f; }

    // clamped per-batch x pointers (invalid tail batches read batch 4095)
    const float* xp[BPW];
    #pragma unroll
    for (int q = 0; q < BPW; q++) {
        int b = b0 + q; if (b > BATCH-1) b = BATCH-1;
        xp[q] = x + (size_t)b * (T_STEPS * 6);
    }

    // biases per lane
    float bi0 = b_ih0[j]    + b_hh0[j];
    float bf0 = b_ih0[32+j] + b_hh0[32+j];
    float bg0 = b_ih0[64+j] + b_hh0[64+j];
    float bo0 = b_ih0[96+j] + b_hh0[96+j];
    float bi1 = b_ih1[j]    + b_hh1[j];
    float bf1 = b_ih1[32+j] + b_hh1[32+j];
    float bg1 = b_ih1[64+j] + b_hh1[64+j];
    float bo1 = b_ih1[96+j] + b_hh1[96+j];

    float c0[BPW], c1[BPW], h1last[BPW];
    #pragma unroll
    for (int q = 0; q < BPW; q++) { c0[q]=0.f; c1[q]=0.f; h1last[q]=0.f; }

    const ulonglong2* Wih0if = (const ulonglong2*)sIh0if;
    const ulonglong2* Wih0go = (const ulonglong2*)sIh0go;
    const ulonglong2* Whh0if = (const ulonglong2*)sHh0if;
    const ulonglong2* Whh0go = (const ulonglong2*)sHh0go;
    const ulonglong2* Wih1if = (const ulonglong2*)sIh1if;
    const ulonglong2* Wih1go = (const ulonglong2*)sIh1go;
    const ulonglong2* Whh1if = (const ulonglong2*)sHh1if;
    const ulonglong2* Whh1go = (const ulonglong2*)sHh1go;

    const uint32_t xs_u32 = (uint32_t)__cvta_generic_to_shared(xs);

    // prologue: load chunk 0 into buffer 0
    {
        #pragma unroll
        for (int r = 0; r < 6; r++) {
            int idx = r * 32 + j;
            if (idx < BPW * 24) {
                int q = idx / 24, f = idx % 24;
                cp_async16(xs_u32 + (uint32_t)(q*96 + f*4) * 4, xp[q] + f*4);
            }
        }
        asm volatile("cp.async.commit_group;");
    }

    int buf = 0;
    for (int tc = 0; tc < NCHUNK; tc++) {
        asm volatile("cp.async.wait_group 0;");
        __syncwarp();
        const float* cur = xs + buf * 672;

        // prefetch next chunk into the other buffer
        if (tc + 1 < NCHUNK) {
            uint32_t dst = xs_u32 + (uint32_t)((buf ^ 1) * 672) * 4;
            const int off = (tc + 1) * 96;
            #pragma unroll
            for (int r = 0; r < 6; r++) {
                int idx = r * 32 + j;
                if (idx < BPW * 24) {
                    int q = idx / 24, f = idx % 24;
                    cp_async16(dst + (uint32_t)(q*96 + f*4) * 4, xp[q] + off + f*4);
                }
            }
            asm volatile("cp.async.commit_group;");
        }

        for (int lt = 0; lt < CHUNK; lt++) {
            unsigned long long ai[BPW], af[BPW], ag[BPW], ao[BPW];
            #pragma unroll
            for (int q = 0; q < BPW; q++) { ai[q]=0ull; af[q]=0ull; ag[q]=0ull; ao[q]=0ull; }

            // ===== Layer 0 : x part (3 kp) =====
            #pragma unroll
            for (int kp = 0; kp < 3; kp++) {
                ulonglong2 wif = Wih0if[kp*32 + j];
                ulonglong2 wgo = Wih0go[kp*32 + j];
                #pragma unroll
                for (int q = 0; q < BPW; q++) {
                    unsigned long long a =
                        *(const unsigned long long*)(cur + q*96 + lt*6 + 2*kp);
                    ai[q] = ffma2(a, wif.x, ai[q]);
                    af[q] = ffma2(a, wif.y, af[q]);
                    ag[q] = ffma2(a, wgo.x, ag[q]);
                    ao[q] = ffma2(a, wgo.y, ao[q]);
                }
            }
            // ===== Layer 0 : h part (16 kp) =====
            #pragma unroll
            for (int m = 0; m < 8; m++) {
                ulonglong2 h[BPW];
                #pragma unroll
                for (int q = 0; q < BPW; q++)
                    h[q] = ((const ulonglong2*)(h0p + q*32))[m];
                #pragma unroll
                for (int s = 0; s < 2; s++) {
                    int kp = 2*m + s;
                    ulonglong2 wif = Whh0if[kp*32 + j];
                    ulonglong2 wgo = Whh0go[kp*32 + j];
                    #pragma unroll
                    for (int q = 0; q < BPW; q++) {
                        unsigned long long a = s ? h[q].y : h[q].x;
                        ai[q] = ffma2(a, wif.x, ai[q]);
                        af[q] = ffma2(a, wif.y, af[q]);
                        ag[q] = ffma2(a, wgo.x, ag[q]);
                        ao[q] = ffma2(a, wgo.y, ao[q]);
                    }
                }
            }
            // activations L0
            float h0new[BPW];
            #pragma unroll
            for (int q = 0; q < BPW; q++) {
                float2 ui = upk2(ai[q]), uf = upk2(af[q]), ug = upk2(ag[q]), uo = upk2(ao[q]);
                float gi = sigf(bi0 + ui.x + ui.y);
                float gf = sigf(bf0 + uf.x + uf.y);
                float gg = tanh_(bg0 + ug.x + ug.y);
                float go = sigf(bo0 + uo.x + uo.y);
                c0[q] = gf * c0[q] + gi * gg;
                h0new[q] = go * tanh_(c0[q]);
            }
            __syncwarp();
            #pragma unroll
            for (int q = 0; q < BPW; q++) h0p[q*32 + j] = h0new[q];
            __syncwarp();

            // ===== Layer 1 =====
            #pragma unroll
            for (int q = 0; q < BPW; q++) { ai[q]=0ull; af[q]=0ull; ag[q]=0ull; ao[q]=0ull; }

            #pragma unroll
            for (int m = 0; m < 8; m++) {
                ulonglong2 h[BPW];
                #pragma unroll
                for (int q = 0; q < BPW; q++)
                    h[q] = ((const ulonglong2*)(h0p + q*32))[m];
                #pragma unroll
                for (int s = 0; s < 2; s++) {
                    int kp = 2*m + s;
                    ulonglong2 wif = Wih1if[kp*32 + j];
                    ulonglong2 wgo = Wih1go[kp*32 + j];
                    #pragma unroll
                    for (int q = 0; q < BPW; q++) {
                        unsigned long long a = s ? h[q].y : h[q].x;
                        ai[q] = ffma2(a, wif.x, ai[q]);
                        af[q] = ffma2(a, wif.y, af[q]);
                        ag[q] = ffma2(a, wgo.x, ag[q]);
                        ao[q] = ffma2(a, wgo.y, ao[q]);
                    }
                }
            }
            #pragma unroll
            for (int m = 0; m < 8; m++) {
                ulonglong2 h[BPW];
                #pragma unroll
                for (int q = 0; q < BPW; q++)
                    h[q] = ((const ulonglong2*)(h1p + q*32))[m];
                #pragma unroll
                for (int s = 0; s < 2; s++) {
                    int kp = 2*m + s;
                    ulonglong2 wif = Whh1if[kp*32 + j];
                    ulonglong2 wgo = Whh1go[kp*32 + j];
                    #pragma unroll
                    for (int q = 0; q < BPW; q++) {
                        unsigned long long a = s ? h[q].y : h[q].x;
                        ai[q] = ffma2(a, wif.x, ai[q]);
                        af[q] = ffma2(a, wif.y, af[q]);
                        ag[q] = ffma2(a, wgo.x, ag[q]);
                        ao[q] = ffma2(a, wgo.y, ao[q]);
                    }
                }
            }
            float h1new[BPW];
            #pragma unroll
            for (int q = 0; q < BPW; q++) {
                float2 ui = upk2(ai[q]), uf = upk2(af[q]), ug = upk2(ag[q]), uo = upk2(ao[q]);
                float gi = sigf(bi1 + ui.x + ui.y);
                float gf = sigf(bf1 + uf.x + uf.y);
                float gg = tanh_(bg1 + ug.x + ug.y);
                float go = sigf(bo1 + uo.x + uo.y);
                c1[q] = gf * c1[q] + gi * gg;
                h1new[q] = go * tanh_(c1[q]);
                h1last[q] = h1new[q];
            }
            __syncwarp();
            #pragma unroll
            for (int q = 0; q < BPW; q++) h1p[q*32 + j] = h1new[q];
            __syncwarp();
        }
        buf ^= 1;
    }

    // ===== final LayerNorm over H=32 =====
    float g = ln_gamma[j];
    float be = ln_beta[j];
    #pragma unroll
    for (int q = 0; q < BPW; q++) {
        if (b0 + q >= BATCH) break;
        float v = h1last[q];
        float s = v;
        #pragma unroll
        for (int o2 = 16; o2 > 0; o2 >>= 1) s += __shfl_xor_sync(0xffffffffu, s, o2);
        float mu = s * (1.0f / 32.0f);
        float dv = v - mu;
        float qq = dv * dv;
        #pragma unroll
        for (int o2 = 16; o2 > 0; o2 >>= 1) qq += __shfl_xor_sync(0xffffffffu, qq, o2);
        float var = qq * (1.0f / 32.0f);
        out[(size_t)(b0 + q) * 32 + j] = dv * rsqrtf(var + 1e-5f) * g + be;
    }
}

extern "C" void kernel_launch(void* const* d_in, const int* in_sizes, int n_in,
                              void* d_out, int out_size)
{
    const float* x      = (const float*)d_in[0];
    const float* W_ih0  = (const float*)d_in[1];
    const float* W_hh0  = (const float*)d_in[2];
    const float* b_ih0  = (const float*)d_in[3];
    const float* b_hh0  = (const float*)d_in[4];
    const float* W_ih1  = (const float*)d_in[5];
    const float* W_hh1  = (const float*)d_in[6];
    const float* b_ih1  = (const float*)d_in[7];
    const float* b_hh1  = (const float*)d_in[8];
    const float* ln_g   = (const float*)d_in[9];
    const float* ln_b   = (const float*)d_in[10];
    float* out = (float*)d_out;

    cudaFuncSetAttribute(lstm_enc_kernel,
                         cudaFuncAttributeMaxDynamicSharedMemorySize, SMEM_BYTES);
    lstm_enc_kernel<<<NUM_CTAS, CTA_THREADS, SMEM_BYTES>>>(
        x, W_ih0, W_hh0, b_ih0, b_hh0, W_ih1, W_hh1, b_ih1, b_hh1,
        ln_g, ln_b, out);
}

// round 4
// speedup vs baseline: 1.1514x; 1.1514x over previous
#include <cuda_runtime.h>
#include <cuda_bf16.h>
#include <cstdint>

// 2-layer LSTM (H=32) + LayerNorm. B=4096, T=512, D=6.
// Round 4: 6 warps/CTA (1.5/SMSP), BPW=5, 137 CTAs. Weights in shared with
// f32x2 k-pair layout; x staged via double-buffered cp.async (16-step chunks).
// Balances smem wavefronts (~3100/step) against FFMA2 issue (~3060/step).

#define T_STEPS 512
#define BATCH 4096
#define BPW 5
#define WARPS_PER_CTA 6
#define CTA_THREADS 192
#define NUM_CTAS 137
#define CHUNK 16
#define NCHUNK (T_STEPS / CHUNK)

// smem floats: weights 13056 ; hbuf 6*(BPW*64)=1920 ; xbuf 6*2*(BPW*96)=5760
#define SMEM_FLOATS (13056 + 1920 + 5760)
#define SMEM_BYTES (SMEM_FLOATS * 4)

__device__ __forceinline__ float2 upk2(unsigned long long v) {
    unsigned int lo, hi;
    asm("mov.b64 {%0,%1}, %2;" : "=r"(lo), "=r"(hi) : "l"(v));
    return make_float2(__uint_as_float(lo), __uint_as_float(hi));
}
__device__ __forceinline__ unsigned long long ffma2(
    unsigned long long a, unsigned long long b, unsigned long long c) {
    unsigned long long d;
    asm("fma.rn.f32x2 %0, %1, %2, %3;" : "=l"(d) : "l"(a), "l"(b), "l"(c));
    return d;
}
__device__ __forceinline__ float sigf(float x) {
    return __fdividef(1.0f, 1.0f + __expf(-x));
}
__device__ __forceinline__ float tanh_(float x) {
    return __fdividef(2.0f, 1.0f + __expf(-2.0f * x)) - 1.0f;
}
__device__ __forceinline__ void cp_async16(uint32_t s, const void* g) {
    asm volatile("cp.async.ca.shared.global [%0], [%1], 16;" :: "r"(s), "l"(g));
}

__global__ __launch_bounds__(CTA_THREADS, 1)
void lstm_enc_kernel(const float* __restrict__ x,
                     const float* __restrict__ W_ih0,
                     const float* __restrict__ W_hh0,
                     const float* __restrict__ b_ih0,
                     const float* __restrict__ b_hh0,
                     const float* __restrict__ W_ih1,
                     const float* __restrict__ W_hh1,
                     const float* __restrict__ b_ih1,
                     const float* __restrict__ b_hh1,
                     const float* __restrict__ ln_gamma,
                     const float* __restrict__ ln_beta,
                     float* __restrict__ out)
{
    extern __shared__ float smem[];
    float* sIh0if = smem;                 // [3kp][32j][4]
    float* sIh0go = sIh0if + 384;
    float* sHh0if = sIh0go + 384;         // [16kp][32j][4]
    float* sHh0go = sHh0if + 2048;
    float* sIh1if = sHh0go + 2048;
    float* sIh1go = sIh1if + 2048;
    float* sHh1if = sIh1go + 2048;
    float* sHh1go = sHh1if + 2048;
    float* hbuf   = sHh1go + 2048;        // 6 warps * (BPW*64)
    float* xbuf   = hbuf + WARPS_PER_CTA * (BPW*64);  // 6 warps * 2 * BPW*96

    const int tid = threadIdx.x;

    // ---- stage weights (k-pair layout): entry (kp*32+j)*4 =
    //  {W[g0*32+j][2kp], W[g0*32+j][2kp+1], W[g1*32+j][2kp], W[g1*32+j][2kp+1]}
    for (int i = tid; i < 512; i += CTA_THREADS) {
        int kp = i >> 5, j = i & 31;
        int k0 = 2 * kp, k1 = k0 + 1;
        ((float4*)sHh0if)[i] = make_float4(W_hh0[(j)*32+k0],    W_hh0[(j)*32+k1],
                                           W_hh0[(32+j)*32+k0], W_hh0[(32+j)*32+k1]);
        ((float4*)sHh0go)[i] = make_float4(W_hh0[(64+j)*32+k0], W_hh0[(64+j)*32+k1],
                                           W_hh0[(96+j)*32+k0], W_hh0[(96+j)*32+k1]);
        ((float4*)sIh1if)[i] = make_float4(W_ih1[(j)*32+k0],    W_ih1[(j)*32+k1],
                                           W_ih1[(32+j)*32+k0], W_ih1[(32+j)*32+k1]);
        ((float4*)sIh1go)[i] = make_float4(W_ih1[(64+j)*32+k0], W_ih1[(64+j)*32+k1],
                                           W_ih1[(96+j)*32+k0], W_ih1[(96+j)*32+k1]);
        ((float4*)sHh1if)[i] = make_float4(W_hh1[(j)*32+k0],    W_hh1[(j)*32+k1],
                                           W_hh1[(32+j)*32+k0], W_hh1[(32+j)*32+k1]);
        ((float4*)sHh1go)[i] = make_float4(W_hh1[(64+j)*32+k0], W_hh1[(64+j)*32+k1],
                                           W_hh1[(96+j)*32+k0], W_hh1[(96+j)*32+k1]);
    }
    for (int i = tid; i < 96; i += CTA_THREADS) {
        int kp = i >> 5, j = i & 31;
        int k0 = 2 * kp, k1 = k0 + 1;
        ((float4*)sIh0if)[i] = make_float4(W_ih0[(j)*6+k0],    W_ih0[(j)*6+k1],
                                           W_ih0[(32+j)*6+k0], W_ih0[(32+j)*6+k1]);
        ((float4*)sIh0go)[i] = make_float4(W_ih0[(64+j)*6+k0], W_ih0[(64+j)*6+k1],
                                           W_ih0[(96+j)*6+k0], W_ih0[(96+j)*6+k1]);
    }
    __syncthreads();

    const int wid = tid >> 5;
    const int j = tid & 31;
    const int task = blockIdx.x * WARPS_PER_CTA + wid;
    const int b0 = task * BPW;

    float* h0p = hbuf + wid * (BPW*64);         // [BPW][32]
    float* h1p = h0p + BPW*32;                  // [BPW][32]
    float* xs  = xbuf + wid * (2*BPW*96);       // 2 x [BPW][96]

    #pragma unroll
    for (int q = 0; q < BPW; q++) { h0p[q*32 + j] = 0.0f; h1p[q*32 + j] = 0.0f; }

    // clamped per-batch x pointers (tail duplicates batch 4095; writes identical)
    const float* xp[BPW];
    #pragma unroll
    for (int q = 0; q < BPW; q++) {
        int b = b0 + q; if (b > BATCH-1) b = BATCH-1;
        xp[q] = x + (size_t)b * (T_STEPS * 6);
    }

    // biases per lane
    float bi0 = b_ih0[j]    + b_hh0[j];
    float bf0 = b_ih0[32+j] + b_hh0[32+j];
    float bg0 = b_ih0[64+j] + b_hh0[64+j];
    float bo0 = b_ih0[96+j] + b_hh0[96+j];
    float bi1 = b_ih1[j]    + b_hh1[j];
    float bf1 = b_ih1[32+j] + b_hh1[32+j];
    float bg1 = b_ih1[64+j] + b_hh1[64+j];
    float bo1 = b_ih1[96+j] + b_hh1[96+j];

    float c0[BPW], c1[BPW], h1last[BPW];
    #pragma unroll
    for (int q = 0; q < BPW; q++) { c0[q]=0.f; c1[q]=0.f; h1last[q]=0.f; }

    const ulonglong2* Wih0if = (const ulonglong2*)sIh0if;
    const ulonglong2* Wih0go = (const ulonglong2*)sIh0go;
    const ulonglong2* Whh0if = (const ulonglong2*)sHh0if;
    const ulonglong2* Whh0go = (const ulonglong2*)sHh0go;
    const ulonglong2* Wih1if = (const ulonglong2*)sIh1if;
    const ulonglong2* Wih1go = (const ulonglong2*)sIh1go;
    const ulonglong2* Whh1if = (const ulonglong2*)sHh1if;
    const ulonglong2* Whh1go = (const ulonglong2*)sHh1go;

    const uint32_t xs_u32 = (uint32_t)__cvta_generic_to_shared(xs);

    // prologue: load chunk 0 into buffer 0 (BPW*24 = 120 float4 per warp)
    {
        #pragma unroll
        for (int r = 0; r < 4; r++) {
            int idx = r * 32 + j;
            if (idx < BPW * 24) {
                int q = idx / 24, f = idx % 24;
                cp_async16(xs_u32 + (uint32_t)(q*96 + f*4) * 4, xp[q] + f*4);
            }
        }
        asm volatile("cp.async.commit_group;");
    }

    int buf = 0;
    for (int tc = 0; tc < NCHUNK; tc++) {
        asm volatile("cp.async.wait_group 0;");
        __syncwarp();
        const float* cur = xs + buf * (BPW*96);

        // prefetch next chunk into the other buffer
        if (tc + 1 < NCHUNK) {
            uint32_t dst = xs_u32 + (uint32_t)((buf ^ 1) * (BPW*96)) * 4;
            const int off = (tc + 1) * 96;
            #pragma unroll
            for (int r = 0; r < 4; r++) {
                int idx = r * 32 + j;
                if (idx < BPW * 24) {
                    int q = idx / 24, f = idx % 24;
                    cp_async16(dst + (uint32_t)(q*96 + f*4) * 4, xp[q] + off + f*4);
                }
            }
            asm volatile("cp.async.commit_group;");
        }

        for (int lt = 0; lt < CHUNK; lt++) {
            unsigned long long ai[BPW], af[BPW], ag[BPW], ao[BPW];
            #pragma unroll
            for (int q = 0; q < BPW; q++) { ai[q]=0ull; af[q]=0ull; ag[q]=0ull; ao[q]=0ull; }

            // ===== Layer 0 : x part (3 kp) =====
            #pragma unroll
            for (int kp = 0; kp < 3; kp++) {
                ulonglong2 wif = Wih0if[kp*32 + j];
                ulonglong2 wgo = Wih0go[kp*32 + j];
                #pragma unroll
                for (int q = 0; q < BPW; q++) {
                    unsigned long long a =
                        *(const unsigned long long*)(cur + q*96 + lt*6 + 2*kp);
                    ai[q] = ffma2(a, wif.x, ai[q]);
                    af[q] = ffma2(a, wif.y, af[q]);
                    ag[q] = ffma2(a, wgo.x, ag[q]);
                    ao[q] = ffma2(a, wgo.y, ao[q]);
                }
            }
            // ===== Layer 0 : h part (16 kp) =====
            #pragma unroll
            for (int m = 0; m < 8; m++) {
                ulonglong2 h[BPW];
                #pragma unroll
                for (int q = 0; q < BPW; q++)
                    h[q] = ((const ulonglong2*)(h0p + q*32))[m];
                #pragma unroll
                for (int s = 0; s < 2; s++) {
                    int kp = 2*m + s;
                    ulonglong2 wif = Whh0if[kp*32 + j];
                    ulonglong2 wgo = Whh0go[kp*32 + j];
                    #pragma unroll
                    for (int q = 0; q < BPW; q++) {
                        unsigned long long a = s ? h[q].y : h[q].x;
                        ai[q] = ffma2(a, wif.x, ai[q]);
                        af[q] = ffma2(a, wif.y, af[q]);
                        ag[q] = ffma2(a, wgo.x, ag[q]);
                        ao[q] = ffma2(a, wgo.y, ao[q]);
                    }
                }
            }
            // activations L0
            float h0new[BPW];
            #pragma unroll
            for (int q = 0; q < BPW; q++) {
                float2 ui = upk2(ai[q]), uf = upk2(af[q]), ug = upk2(ag[q]), uo = upk2(ao[q]);
                float gi = sigf(bi0 + ui.x + ui.y);
                float gf = sigf(bf0 + uf.x + uf.y);
                float gg = tanh_(bg0 + ug.x + ug.y);
                float go = sigf(bo0 + uo.x + uo.y);
                c0[q] = gf * c0[q] + gi * gg;
                h0new[q] = go * tanh_(c0[q]);
            }
            __syncwarp();
            #pragma unroll
            for (int q = 0; q < BPW; q++) h0p[q*32 + j] = h0new[q];
            __syncwarp();

            // ===== Layer 1 =====
            #pragma unroll
            for (int q = 0; q < BPW; q++) { ai[q]=0ull; af[q]=0ull; ag[q]=0ull; ao[q]=0ull; }

            #pragma unroll
            for (int m = 0; m < 8; m++) {
                ulonglong2 h[BPW];
                #pragma unroll
                for (int q = 0; q < BPW; q++)
                    h[q] = ((const ulonglong2*)(h0p + q*32))[m];
                #pragma unroll
                for (int s = 0; s < 2; s++) {
                    int kp = 2*m + s;
                    ulonglong2 wif = Wih1if[kp*32 + j];
                    ulonglong2 wgo = Wih1go[kp*32 + j];
                    #pragma unroll
                    for (int q = 0; q < BPW; q++) {
                        unsigned long long a = s ? h[q].y : h[q].x;
                        ai[q] = ffma2(a, wif.x, ai[q]);
                        af[q] = ffma2(a, wif.y, af[q]);
                        ag[q] = ffma2(a, wgo.x, ag[q]);
                        ao[q] = ffma2(a, wgo.y, ao[q]);
                    }
                }
            }
            #pragma unroll
            for (int m = 0; m < 8; m++) {
                ulonglong2 h[BPW];
                #pragma unroll
                for (int q = 0; q < BPW; q++)
                    h[q] = ((const ulonglong2*)(h1p + q*32))[m];
                #pragma unroll
                for (int s = 0; s < 2; s++) {
                    int kp = 2*m + s;
                    ulonglong2 wif = Whh1if[kp*32 + j];
                    ulonglong2 wgo = Whh1go[kp*32 + j];
                    #pragma unroll
                    for (int q = 0; q < BPW; q++) {
                        unsigned long long a = s ? h[q].y : h[q].x;
                        ai[q] = ffma2(a, wif.x, ai[q]);
                        af[q] = ffma2(a, wif.y, af[q]);
                        ag[q] = ffma2(a, wgo.x, ag[q]);
                        ao[q] = ffma2(a, wgo.y, ao[q]);
                    }
                }
            }
            float h1new[BPW];
            #pragma unroll
            for (int q = 0; q < BPW; q++) {
                float2 ui = upk2(ai[q]), uf = upk2(af[q]), ug = upk2(ag[q]), uo = upk2(ao[q]);
                float gi = sigf(bi1 + ui.x + ui.y);
                float gf = sigf(bf1 + uf.x + uf.y);
                float gg = tanh_(bg1 + ug.x + ug.y);
                float go = sigf(bo1 + uo.x + uo.y);
                c1[q] = gf * c1[q] + gi * gg;
                h1new[q] = go * tanh_(c1[q]);
                h1last[q] = h1new[q];
            }
            __syncwarp();
            #pragma unroll
            for (int q = 0; q < BPW; q++) h1p[q*32 + j] = h1new[q];
            __syncwarp();
        }
        buf ^= 1;
    }

    // ===== final LayerNorm over H=32 =====
    float g = ln_gamma[j];
    float be = ln_beta[j];
    #pragma unroll
    for (int q = 0; q < BPW; q++) {
        if (b0 + q >= BATCH) break;
        float v = h1last[q];
        float s = v;
        #pragma unroll
        for (int o2 = 16; o2 > 0; o2 >>= 1) s += __shfl_xor_sync(0xffffffffu, s, o2);
        float mu = s * (1.0f / 32.0f);
        float dv = v - mu;
        float qq = dv * dv;
        #pragma unroll
        for (int o2 = 16; o2 > 0; o2 >>= 1) qq += __shfl_xor_sync(0xffffffffu, qq, o2);
        float var = qq * (1.0f / 32.0f);
        out[(size_t)(b0 + q) * 32 + j] = dv * rsqrtf(var + 1e-5f) * g + be;
    }
}

extern "C" void kernel_launch(void* const* d_in, const int* in_sizes, int n_in,
                              void* d_out, int out_size)
{
    const float* x      = (const float*)d_in[0];
    const float* W_ih0  = (const float*)d_in[1];
    const float* W_hh0  = (const float*)d_in[2];
    const float* b_ih0  = (const float*)d_in[3];
    const float* b_hh0  = (const float*)d_in[4];
    const float* W_ih1  = (const float*)d_in[5];
    const float* W_hh1  = (const float*)d_in[6];
    const float* b_ih1  = (const float*)d_in[7];
    const float* b_hh1  = (const float*)d_in[8];
    const float* ln_g   = (const float*)d_in[9];
    const float* ln_b   = (const float*)d_in[10];
    float* out = (float*)d_out;

    cudaFuncSetAttribute(lstm_enc_kernel,
                         cudaFuncAttributeMaxDynamicSharedMemorySize, SMEM_BYTES);
    lstm_enc_kernel<<<NUM_CTAS, CTA_THREADS, SMEM_BYTES>>>(
        x, W_ih0, W_hh0, b_ih0, b_hh0, W_ih1, W_hh1, b_ih1, b_hh1,
        ln_g, ln_b, out);
}

// round 5
// speedup vs baseline: 1.5228x; 1.3226x over previous
#include <cuda_runtime.h>
#include <cuda_bf16.h>
#include <cstdint>

// 2-layer LSTM (H=32) + LayerNorm. B=4096, T=512, D=6.
// Round 5: R2 config (147 CTAs x 7 warps, BPW=4) + tanh.approx activations
// (1 MUFU each, no rcp chain) + parity double-buffered h (1 syncwarp/step)
// + cp.async x staging. Weights in shared, f32x2 k-pair layout.

#define T_STEPS 512
#define BATCH 4096
#define BPW 4
#define WARPS_PER_CTA 7
#define CTA_THREADS 224
#define NUM_CTAS 147
#define CHUNK 16
#define NCHUNK (T_STEPS / CHUNK)

// smem floats: weights 13056 ; hbuf 7*512 = 3584 ; xbuf 7*2*384 = 5376
#define SMEM_FLOATS (13056 + 3584 + 5376)
#define SMEM_BYTES (SMEM_FLOATS * 4)

__device__ __forceinline__ float2 upk2(unsigned long long v) {
    unsigned int lo, hi;
    asm("mov.b64 {%0,%1}, %2;" : "=r"(lo), "=r"(hi) : "l"(v));
    return make_float2(__uint_as_float(lo), __uint_as_float(hi));
}
__device__ __forceinline__ unsigned long long ffma2(
    unsigned long long a, unsigned long long b, unsigned long long c) {
    unsigned long long d;
    asm("fma.rn.f32x2 %0, %1, %2, %3;" : "=l"(d) : "l"(a), "l"(b), "l"(c));
    return d;
}
__device__ __forceinline__ float tanhap(float x) {
    float r;
    asm("tanh.approx.f32 %0, %1;" : "=f"(r) : "f"(x));
    return r;
}
__device__ __forceinline__ float sigap(float x) {
    return fmaf(0.5f, tanhap(0.5f * x), 0.5f);
}
__device__ __forceinline__ void cp_async16(uint32_t s, const void* g) {
    asm volatile("cp.async.ca.shared.global [%0], [%1], 16;" :: "r"(s), "l"(g));
}

__global__ __launch_bounds__(CTA_THREADS, 1)
void lstm_enc_kernel(const float* __restrict__ x,
                     const float* __restrict__ W_ih0,
                     const float* __restrict__ W_hh0,
                     const float* __restrict__ b_ih0,
                     const float* __restrict__ b_hh0,
                     const float* __restrict__ W_ih1,
                     const float* __restrict__ W_hh1,
                     const float* __restrict__ b_ih1,
                     const float* __restrict__ b_hh1,
                     const float* __restrict__ ln_gamma,
                     const float* __restrict__ ln_beta,
                     float* __restrict__ out)
{
    extern __shared__ float smem[];
    float* sIh0if = smem;                 // [3kp][32j][4]
    float* sIh0go = sIh0if + 384;
    float* sHh0if = sIh0go + 384;         // [16kp][32j][4]
    float* sHh0go = sHh0if + 2048;
    float* sIh1if = sHh0go + 2048;
    float* sIh1go = sIh1if + 2048;
    float* sHh1if = sIh1go + 2048;
    float* sHh1go = sHh1if + 2048;
    float* hbuf   = sHh1go + 2048;        // 7 warps * 512: h0[2][4][32], h1[2][4][32]
    float* xbuf   = hbuf + WARPS_PER_CTA * 512;  // 7 warps * 2 * 384

    const int tid = threadIdx.x;

    // ---- stage weights (k-pair layout): entry (kp*32+j)*4 =
    //  {W[g0*32+j][2kp], W[g0*32+j][2kp+1], W[g1*32+j][2kp], W[g1*32+j][2kp+1]}
    for (int i = tid; i < 512; i += CTA_THREADS) {
        int kp = i >> 5, j = i & 31;
        int k0 = 2 * kp, k1 = k0 + 1;
        ((float4*)sHh0if)[i] = make_float4(W_hh0[(j)*32+k0],    W_hh0[(j)*32+k1],
                                           W_hh0[(32+j)*32+k0], W_hh0[(32+j)*32+k1]);
        ((float4*)sHh0go)[i] = make_float4(W_hh0[(64+j)*32+k0], W_hh0[(64+j)*32+k1],
                                           W_hh0[(96+j)*32+k0], W_hh0[(96+j)*32+k1]);
        ((float4*)sIh1if)[i] = make_float4(W_ih1[(j)*32+k0],    W_ih1[(j)*32+k1],
                                           W_ih1[(32+j)*32+k0], W_ih1[(32+j)*32+k1]);
        ((float4*)sIh1go)[i] = make_float4(W_ih1[(64+j)*32+k0], W_ih1[(64+j)*32+k1],
                                           W_ih1[(96+j)*32+k0], W_ih1[(96+j)*32+k1]);
        ((float4*)sHh1if)[i] = make_float4(W_hh1[(j)*32+k0],    W_hh1[(j)*32+k1],
                                           W_hh1[(32+j)*32+k0], W_hh1[(32+j)*32+k1]);
        ((float4*)sHh1go)[i] = make_float4(W_hh1[(64+j)*32+k0], W_hh1[(64+j)*32+k1],
                                           W_hh1[(96+j)*32+k0], W_hh1[(96+j)*32+k1]);
    }
    for (int i = tid; i < 96; i += CTA_THREADS) {
        int kp = i >> 5, j = i & 31;
        int k0 = 2 * kp, k1 = k0 + 1;
        ((float4*)sIh0if)[i] = make_float4(W_ih0[(j)*6+k0],    W_ih0[(j)*6+k1],
                                           W_ih0[(32+j)*6+k0], W_ih0[(32+j)*6+k1]);
        ((float4*)sIh0go)[i] = make_float4(W_ih0[(64+j)*6+k0], W_ih0[(64+j)*6+k1],
                                           W_ih0[(96+j)*6+k0], W_ih0[(96+j)*6+k1]);
    }
    __syncthreads();

    const int wid = tid >> 5;
    const int j = tid & 31;
    const int task = blockIdx.x * WARPS_PER_CTA + wid;
    if (task * BPW >= BATCH) return;
    const int b0 = task * BPW;

    // parity double-buffered h: h0[p] at wid*512 + p*128; h1[p] at +256 + p*128
    float* h0b = hbuf + wid * 512;
    float* h1b = h0b + 256;
    float* xs  = xbuf + wid * 768;        // 2 x [4][96]

    #pragma unroll
    for (int p = 0; p < 2; p++)
        #pragma unroll
        for (int q = 0; q < BPW; q++) {
            h0b[p*128 + q*32 + j] = 0.0f;
            h1b[p*128 + q*32 + j] = 0.0f;
        }

    // clamped per-batch x pointers (tail duplicates batch 4095)
    const float* xp[BPW];
    #pragma unroll
    for (int q = 0; q < BPW; q++) {
        int b = b0 + q; if (b > BATCH-1) b = BATCH-1;
        xp[q] = x + (size_t)b * (T_STEPS * 6);
    }

    float bi0 = b_ih0[j]    + b_hh0[j];
    float bf0 = b_ih0[32+j] + b_hh0[32+j];
    float bg0 = b_ih0[64+j] + b_hh0[64+j];
    float bo0 = b_ih0[96+j] + b_hh0[96+j];
    float bi1 = b_ih1[j]    + b_hh1[j];
    float bf1 = b_ih1[32+j] + b_hh1[32+j];
    float bg1 = b_ih1[64+j] + b_hh1[64+j];
    float bo1 = b_ih1[96+j] + b_hh1[96+j];

    float c0[BPW], c1[BPW], h1last[BPW];
    #pragma unroll
    for (int q = 0; q < BPW; q++) { c0[q]=0.f; c1[q]=0.f; h1last[q]=0.f; }

    const ulonglong2* Wih0if = (const ulonglong2*)sIh0if;
    const ulonglong2* Wih0go = (const ulonglong2*)sIh0go;
    const ulonglong2* Whh0if = (const ulonglong2*)sHh0if;
    const ulonglong2* Whh0go = (const ulonglong2*)sHh0go;
    const ulonglong2* Wih1if = (const ulonglong2*)sIh1if;
    const ulonglong2* Wih1go = (const ulonglong2*)sIh1go;
    const ulonglong2* Whh1if = (const ulonglong2*)sHh1if;
    const ulonglong2* Whh1go = (const ulonglong2*)sHh1go;

    const uint32_t xs_u32 = (uint32_t)__cvta_generic_to_shared(xs);

    // prologue: chunk 0 -> buffer 0.  BPW*24 = 96 float4 = 3 warp-rows exactly.
    {
        #pragma unroll
        for (int r = 0; r < 3; r++) {
            int idx = r * 32 + j;
            int q = idx / 24, f = idx % 24;
            cp_async16(xs_u32 + (uint32_t)(q*96 + f*4) * 4, xp[q] + f*4);
        }
        asm volatile("cp.async.commit_group;");
    }

    int buf = 0;
    for (int tc = 0; tc < NCHUNK; tc++) {
        asm volatile("cp.async.wait_group 0;");
        __syncwarp();
        const float* cur = xs + buf * 384;

        if (tc + 1 < NCHUNK) {
            uint32_t dst = xs_u32 + (uint32_t)((buf ^ 1) * 384) * 4;
            const int off = (tc + 1) * 96;
            #pragma unroll
            for (int r = 0; r < 3; r++) {
                int idx = r * 32 + j;
                int q = idx / 24, f = idx % 24;
                cp_async16(dst + (uint32_t)(q*96 + f*4) * 4, xp[q] + off + f*4);
            }
            asm volatile("cp.async.commit_group;");
        }

        for (int lt = 0; lt < CHUNK; lt++) {
            const int t = tc * CHUNK + lt;
            const int p = t & 1;             // write parity
            const float* h0rd = h0b + (p^1) * 128;   // h0(t-1)
            float*       h0wr = h0b + p * 128;
            const float* h1rd = h1b + (p^1) * 128;   // h1(t-1)
            float*       h1wr = h1b + p * 128;

            unsigned long long ai[BPW], af[BPW], ag[BPW], ao[BPW];
            #pragma unroll
            for (int q = 0; q < BPW; q++) { ai[q]=0ull; af[q]=0ull; ag[q]=0ull; ao[q]=0ull; }

            // ===== Layer 0 : x part (3 kp) =====
            #pragma unroll
            for (int kp = 0; kp < 3; kp++) {
                ulonglong2 wif = Wih0if[kp*32 + j];
                ulonglong2 wgo = Wih0go[kp*32 + j];
                #pragma unroll
                for (int q = 0; q < BPW; q++) {
                    unsigned long long a =
                        *(const unsigned long long*)(cur + q*96 + lt*6 + 2*kp);
                    ai[q] = ffma2(a, wif.x, ai[q]);
                    af[q] = ffma2(a, wif.y, af[q]);
                    ag[q] = ffma2(a, wgo.x, ag[q]);
                    ao[q] = ffma2(a, wgo.y, ao[q]);
                }
            }
            // ===== Layer 0 : h part (16 kp) =====
            #pragma unroll
            for (int m = 0; m < 8; m++) {
                ulonglong2 h[BPW];
                #pragma unroll
                for (int q = 0; q < BPW; q++)
                    h[q] = ((const ulonglong2*)(h0rd + q*32))[m];
                #pragma unroll
                for (int s = 0; s < 2; s++) {
                    int kp = 2*m + s;
                    ulonglong2 wif = Whh0if[kp*32 + j];
                    ulonglong2 wgo = Whh0go[kp*32 + j];
                    #pragma unroll
                    for (int q = 0; q < BPW; q++) {
                        unsigned long long a = s ? h[q].y : h[q].x;
                        ai[q] = ffma2(a, wif.x, ai[q]);
                        af[q] = ffma2(a, wif.y, af[q]);
                        ag[q] = ffma2(a, wgo.x, ag[q]);
                        ao[q] = ffma2(a, wgo.y, ao[q]);
                    }
                }
            }
            // activations L0 (tanh.approx)
            #pragma unroll
            for (int q = 0; q < BPW; q++) {
                float2 ui = upk2(ai[q]), uf = upk2(af[q]), ug = upk2(ag[q]), uo = upk2(ao[q]);
                float gi = sigap(bi0 + ui.x + ui.y);
                float gf = sigap(bf0 + uf.x + uf.y);
                float gg = tanhap(bg0 + ug.x + ug.y);
                float go = sigap(bo0 + uo.x + uo.y);
                c0[q] = gf * c0[q] + gi * gg;
                h0wr[q*32 + j] = go * tanhap(c0[q]);
            }
            __syncwarp();    // the single per-step barrier

            // ===== Layer 1 =====
            #pragma unroll
            for (int q = 0; q < BPW; q++) { ai[q]=0ull; af[q]=0ull; ag[q]=0ull; ao[q]=0ull; }

            #pragma unroll
            for (int m = 0; m < 8; m++) {
                ulonglong2 h[BPW];
                #pragma unroll
                for (int q = 0; q < BPW; q++)
                    h[q] = ((const ulonglong2*)(h0wr + q*32))[m];
                #pragma unroll
                for (int s = 0; s < 2; s++) {
                    int kp = 2*m + s;
                    ulonglong2 wif = Wih1if[kp*32 + j];
                    ulonglong2 wgo = Wih1go[kp*32 + j];
                    #pragma unroll
                    for (int q = 0; q < BPW; q++) {
                        unsigned long long a = s ? h[q].y : h[q].x;
                        ai[q] = ffma2(a, wif.x, ai[q]);
                        af[q] = ffma2(a, wif.y, af[q]);
                        ag[q] = ffma2(a, wgo.x, ag[q]);
                        ao[q] = ffma2(a, wgo.y, ao[q]);
                    }
                }
            }
            #pragma unroll
            for (int m = 0; m < 8; m++) {
                ulonglong2 h[BPW];
                #pragma unroll
                for (int q = 0; q < BPW; q++)
                    h[q] = ((const ulonglong2*)(h1rd + q*32))[m];
                #pragma unroll
                for (int s = 0; s < 2; s++) {
                    int kp = 2*m + s;
                    ulonglong2 wif = Whh1if[kp*32 + j];
                    ulonglong2 wgo = Whh1go[kp*32 + j];
                    #pragma unroll
                    for (int q = 0; q < BPW; q++) {
                        unsigned long long a = s ? h[q].y : h[q].x;
                        ai[q] = ffma2(a, wif.x, ai[q]);
                        af[q] = ffma2(a, wif.y, af[q]);
                        ag[q] = ffma2(a, wgo.x, ag[q]);
                        ao[q] = ffma2(a, wgo.y, ao[q]);
                    }
                }
            }
            #pragma unroll
            for (int q = 0; q < BPW; q++) {
                float2 ui = upk2(ai[q]), uf = upk2(af[q]), ug = upk2(ag[q]), uo = upk2(ao[q]);
                float gi = sigap(bi1 + ui.x + ui.y);
                float gf = sigap(bf1 + uf.x + uf.y);
                float gg = tanhap(bg1 + ug.x + ug.y);
                float go = sigap(bo1 + uo.x + uo.y);
                c1[q] = gf * c1[q] + gi * gg;
                float hn = go * tanhap(c1[q]);
                h1wr[q*32 + j] = hn;
                h1last[q] = hn;
            }
            // no second syncwarp: next step's post-L0 barrier orders h1 stores
        }
        buf ^= 1;
    }

    // ===== final LayerNorm over H=32 =====
    float g = ln_gamma[j];
    float be = ln_beta[j];
    #pragma unroll
    for (int q = 0; q < BPW; q++) {
        if (b0 + q >= BATCH) break;
        float v = h1last[q];
        float s = v;
        #pragma unroll
        for (int o2 = 16; o2 > 0; o2 >>= 1) s += __shfl_xor_sync(0xffffffffu, s, o2);
        float mu = s * (1.0f / 32.0f);
        float dv = v - mu;
        float qq = dv * dv;
        #pragma unroll
        for (int o2 = 16; o2 > 0; o2 >>= 1) qq += __shfl_xor_sync(0xffffffffu, qq, o2);
        float var = qq * (1.0f / 32.0f);
        out[(size_t)(b0 + q) * 32 + j] = dv * rsqrtf(var + 1e-5f) * g + be;
    }
}

extern "C" void kernel_launch(void* const* d_in, const int* in_sizes, int n_in,
                              void* d_out, int out_size)
{
    const float* x      = (const float*)d_in[0];
    const float* W_ih0  = (const float*)d_in[1];
    const float* W_hh0  = (const float*)d_in[2];
    const float* b_ih0  = (const float*)d_in[3];
    const float* b_hh0  = (const float*)d_in[4];
    const float* W_ih1  = (const float*)d_in[5];
    const float* W_hh1  = (const float*)d_in[6];
    const float* b_ih1  = (const float*)d_in[7];
    const float* b_hh1  = (const float*)d_in[8];
    const float* ln_g   = (const float*)d_in[9];
    const float* ln_b   = (const float*)d_in[10];
    float* out = (float*)d_out;

    cudaFuncSetAttribute(lstm_enc_kernel,
                         cudaFuncAttributeMaxDynamicSharedMemorySize, SMEM_BYTES);
    lstm_enc_kernel<<<NUM_CTAS, CTA_THREADS, SMEM_BYTES>>>(
        x, W_ih0, W_hh0, b_ih0, b_hh0, W_ih1, W_hh1, b_ih1, b_hh1,
        ln_g, ln_b, out);
}

// round 6
// speedup vs baseline: 1.5673x; 1.0292x over previous
#include <cuda_runtime.h>
#include <cuda_bf16.h>
#include <cstdint>

// 2-layer LSTM (H=32) + LayerNorm. B=4096, T=512, D=6.
// Round 6: R5 base (147 CTAs x 7 warps, BPW=4, tanh.approx, parity h-buffers,
// cp.async x staging) + register-cached Wih0 & Whh0[kp0..7] (88 regs, -17%
// smem wavefronts) + biases folded into accumulator init.

#define T_STEPS 512
#define BATCH 4096
#define BPW 4
#define WARPS_PER_CTA 7
#define CTA_THREADS 224
#define NUM_CTAS 147
#define CHUNK 16
#define NCHUNK (T_STEPS / CHUNK)

// smem floats: weights 13056 ; hbuf 7*512 = 3584 ; xbuf 7*2*384 = 5376
#define SMEM_FLOATS (13056 + 3584 + 5376)
#define SMEM_BYTES (SMEM_FLOATS * 4)

__device__ __forceinline__ unsigned long long pk2(float lo, float hi) {
    unsigned long long r;
    asm("mov.b64 %0, {%1,%2};" : "=l"(r)
        : "r"(__float_as_uint(lo)), "r"(__float_as_uint(hi)));
    return r;
}
__device__ __forceinline__ float2 upk2(unsigned long long v) {
    unsigned int lo, hi;
    asm("mov.b64 {%0,%1}, %2;" : "=r"(lo), "=r"(hi) : "l"(v));
    return make_float2(__uint_as_float(lo), __uint_as_float(hi));
}
__device__ __forceinline__ unsigned long long ffma2(
    unsigned long long a, unsigned long long b, unsigned long long c) {
    unsigned long long d;
    asm("fma.rn.f32x2 %0, %1, %2, %3;" : "=l"(d) : "l"(a), "l"(b), "l"(c));
    return d;
}
__device__ __forceinline__ float tanhap(float x) {
    float r;
    asm("tanh.approx.f32 %0, %1;" : "=f"(r) : "f"(x));
    return r;
}
__device__ __forceinline__ float sigap(float x) {
    return fmaf(0.5f, tanhap(0.5f * x), 0.5f);
}
__device__ __forceinline__ void cp_async16(uint32_t s, const void* g) {
    asm volatile("cp.async.ca.shared.global [%0], [%1], 16;" :: "r"(s), "l"(g));
}

__global__ __launch_bounds__(CTA_THREADS, 1)
void lstm_enc_kernel(const float* __restrict__ x,
                     const float* __restrict__ W_ih0,
                     const float* __restrict__ W_hh0,
                     const float* __restrict__ b_ih0,
                     const float* __restrict__ b_hh0,
                     const float* __restrict__ W_ih1,
                     const float* __restrict__ W_hh1,
                     const float* __restrict__ b_ih1,
                     const float* __restrict__ b_hh1,
                     const float* __restrict__ ln_gamma,
                     const float* __restrict__ ln_beta,
                     float* __restrict__ out)
{
    extern __shared__ float smem[];
    float* sIh0if = smem;                 // [3kp][32j][4]
    float* sIh0go = sIh0if + 384;
    float* sHh0if = sIh0go + 384;         // [16kp][32j][4]
    float* sHh0go = sHh0if + 2048;
    float* sIh1if = sHh0go + 2048;
    float* sIh1go = sIh1if + 2048;
    float* sHh1if = sIh1go + 2048;
    float* sHh1go = sHh1if + 2048;
    float* hbuf   = sHh1go + 2048;        // 7 warps * 512
    float* xbuf   = hbuf + WARPS_PER_CTA * 512;

    const int tid = threadIdx.x;

    // ---- stage weights (k-pair layout): entry (kp*32+j)*4 =
    //  {W[g0*32+j][2kp], W[g0*32+j][2kp+1], W[g1*32+j][2kp], W[g1*32+j][2kp+1]}
    for (int i = tid; i < 512; i += CTA_THREADS) {
        int kp = i >> 5, j = i & 31;
        int k0 = 2 * kp, k1 = k0 + 1;
        ((float4*)sHh0if)[i] = make_float4(W_hh0[(j)*32+k0],    W_hh0[(j)*32+k1],
                                           W_hh0[(32+j)*32+k0], W_hh0[(32+j)*32+k1]);
        ((float4*)sHh0go)[i] = make_float4(W_hh0[(64+j)*32+k0], W_hh0[(64+j)*32+k1],
                                           W_hh0[(96+j)*32+k0], W_hh0[(96+j)*32+k1]);
        ((float4*)sIh1if)[i] = make_float4(W_ih1[(j)*32+k0],    W_ih1[(j)*32+k1],
                                           W_ih1[(32+j)*32+k0], W_ih1[(32+j)*32+k1]);
        ((float4*)sIh1go)[i] = make_float4(W_ih1[(64+j)*32+k0], W_ih1[(64+j)*32+k1],
                                           W_ih1[(96+j)*32+k0], W_ih1[(96+j)*32+k1]);
        ((float4*)sHh1if)[i] = make_float4(W_hh1[(j)*32+k0],    W_hh1[(j)*32+k1],
                                           W_hh1[(32+j)*32+k0], W_hh1[(32+j)*32+k1]);
        ((float4*)sHh1go)[i] = make_float4(W_hh1[(64+j)*32+k0], W_hh1[(64+j)*32+k1],
                                           W_hh1[(96+j)*32+k0], W_hh1[(96+j)*32+k1]);
    }
    for (int i = tid; i < 96; i += CTA_THREADS) {
        int kp = i >> 5, j = i & 31;
        int k0 = 2 * kp, k1 = k0 + 1;
        ((float4*)sIh0if)[i] = make_float4(W_ih0[(j)*6+k0],    W_ih0[(j)*6+k1],
                                           W_ih0[(32+j)*6+k0], W_ih0[(32+j)*6+k1]);
        ((float4*)sIh0go)[i] = make_float4(W_ih0[(64+j)*6+k0], W_ih0[(64+j)*6+k1],
                                           W_ih0[(96+j)*6+k0], W_ih0[(96+j)*6+k1]);
    }
    __syncthreads();

    const int wid = tid >> 5;
    const int j = tid & 31;
    const int task = blockIdx.x * WARPS_PER_CTA + wid;
    if (task * BPW >= BATCH) return;
    const int b0 = task * BPW;

    float* h0b = hbuf + wid * 512;
    float* h1b = h0b + 256;
    float* xs  = xbuf + wid * 768;

    #pragma unroll
    for (int p = 0; p < 2; p++)
        #pragma unroll
        for (int q = 0; q < BPW; q++) {
            h0b[p*128 + q*32 + j] = 0.0f;
            h1b[p*128 + q*32 + j] = 0.0f;
        }

    const float* xp[BPW];
    #pragma unroll
    for (int q = 0; q < BPW; q++) {
        int b = b0 + q; if (b > BATCH-1) b = BATCH-1;
        xp[q] = x + (size_t)b * (T_STEPS * 6);
    }

    float bi0 = b_ih0[j]    + b_hh0[j];
    float bf0 = b_ih0[32+j] + b_hh0[32+j];
    float bg0 = b_ih0[64+j] + b_hh0[64+j];
    float bo0 = b_ih0[96+j] + b_hh0[96+j];
    float bi1 = b_ih1[j]    + b_hh1[j];
    float bf1 = b_ih1[32+j] + b_hh1[32+j];
    float bg1 = b_ih1[64+j] + b_hh1[64+j];
    float bo1 = b_ih1[96+j] + b_hh1[96+j];

    float c0[BPW], c1[BPW], h1last[BPW];
    #pragma unroll
    for (int q = 0; q < BPW; q++) { c0[q]=0.f; c1[q]=0.f; h1last[q]=0.f; }

    const ulonglong2* Wih0if = (const ulonglong2*)sIh0if;
    const ulonglong2* Wih0go = (const ulonglong2*)sIh0go;
    const ulonglong2* Whh0if = (const ulonglong2*)sHh0if;
    const ulonglong2* Whh0go = (const ulonglong2*)sHh0go;
    const ulonglong2* Wih1if = (const ulonglong2*)sIh1if;
    const ulonglong2* Wih1go = (const ulonglong2*)sIh1go;
    const ulonglong2* Whh1if = (const ulonglong2*)sHh1if;
    const ulonglong2* Whh1go = (const ulonglong2*)sHh1go;

    // ---- register-cache: Wih0 (3 kp) + Whh0 kp 0..7 (88 regs/lane) ----
    ulonglong2 rIf[3], rGo[3], rHif[8], rHgo[8];
    #pragma unroll
    for (int kp = 0; kp < 3; kp++) { rIf[kp] = Wih0if[kp*32 + j]; rGo[kp] = Wih0go[kp*32 + j]; }
    #pragma unroll
    for (int kp = 0; kp < 8; kp++) { rHif[kp] = Whh0if[kp*32 + j]; rHgo[kp] = Whh0go[kp*32 + j]; }

    const uint32_t xs_u32 = (uint32_t)__cvta_generic_to_shared(xs);

    // prologue: chunk 0 -> buffer 0.  BPW*24 = 96 float4 = 3 warp-rows exactly.
    {
        #pragma unroll
        for (int r = 0; r < 3; r++) {
            int idx = r * 32 + j;
            int q = idx / 24, f = idx % 24;
            cp_async16(xs_u32 + (uint32_t)(q*96 + f*4) * 4, xp[q] + f*4);
        }
        asm volatile("cp.async.commit_group;");
    }

    int buf = 0;
    for (int tc = 0; tc < NCHUNK; tc++) {
        asm volatile("cp.async.wait_group 0;");
        __syncwarp();
        const float* cur = xs + buf * 384;

        if (tc + 1 < NCHUNK) {
            uint32_t dst = xs_u32 + (uint32_t)((buf ^ 1) * 384) * 4;
            const int off = (tc + 1) * 96;
            #pragma unroll
            for (int r = 0; r < 3; r++) {
                int idx = r * 32 + j;
                int q = idx / 24, f = idx % 24;
                cp_async16(dst + (uint32_t)(q*96 + f*4) * 4, xp[q] + off + f*4);
            }
            asm volatile("cp.async.commit_group;");
        }

        for (int lt = 0; lt < CHUNK; lt++) {
            const int t = tc * CHUNK + lt;
            const int p = t & 1;
            const float* h0rd = h0b + (p^1) * 128;
            float*       h0wr = h0b + p * 128;
            const float* h1rd = h1b + (p^1) * 128;
            float*       h1wr = h1b + p * 128;

            // biases folded into accumulator init (lo half)
            unsigned long long ai[BPW], af[BPW], ag[BPW], ao[BPW];
            #pragma unroll
            for (int q = 0; q < BPW; q++) {
                ai[q] = pk2(bi0, 0.f); af[q] = pk2(bf0, 0.f);
                ag[q] = pk2(bg0, 0.f); ao[q] = pk2(bo0, 0.f);
            }

            // ===== Layer 0 : x part (3 kp, register weights) =====
            #pragma unroll
            for (int kp = 0; kp < 3; kp++) {
                #pragma unroll
                for (int q = 0; q < BPW; q++) {
                    unsigned long long a =
                        *(const unsigned long long*)(cur + q*96 + lt*6 + 2*kp);
                    ai[q] = ffma2(a, rIf[kp].x, ai[q]);
                    af[q] = ffma2(a, rIf[kp].y, af[q]);
                    ag[q] = ffma2(a, rGo[kp].x, ag[q]);
                    ao[q] = ffma2(a, rGo[kp].y, ao[q]);
                }
            }
            // ===== Layer 0 : h part kp 0..7 (register weights) =====
            #pragma unroll
            for (int m = 0; m < 4; m++) {
                ulonglong2 h[BPW];
                #pragma unroll
                for (int q = 0; q < BPW; q++)
                    h[q] = ((const ulonglong2*)(h0rd + q*32))[m];
                #pragma unroll
                for (int s = 0; s < 2; s++) {
                    int kp = 2*m + s;
                    #pragma unroll
                    for (int q = 0; q < BPW; q++) {
                        unsigned long long a = s ? h[q].y : h[q].x;
                        ai[q] = ffma2(a, rHif[kp].x, ai[q]);
                        af[q] = ffma2(a, rHif[kp].y, af[q]);
                        ag[q] = ffma2(a, rHgo[kp].x, ag[q]);
                        ao[q] = ffma2(a, rHgo[kp].y, ao[q]);
                    }
                }
            }
            // ===== Layer 0 : h part kp 8..15 (smem weights) =====
            #pragma unroll
            for (int m = 4; m < 8; m++) {
                ulonglong2 h[BPW];
                #pragma unroll
                for (int q = 0; q < BPW; q++)
                    h[q] = ((const ulonglong2*)(h0rd + q*32))[m];
                #pragma unroll
                for (int s = 0; s < 2; s++) {
                    int kp = 2*m + s;
                    ulonglong2 wif = Whh0if[kp*32 + j];
                    ulonglong2 wgo = Whh0go[kp*32 + j];
                    #pragma unroll
                    for (int q = 0; q < BPW; q++) {
                        unsigned long long a = s ? h[q].y : h[q].x;
                        ai[q] = ffma2(a, wif.x, ai[q]);
                        af[q] = ffma2(a, wif.y, af[q]);
                        ag[q] = ffma2(a, wgo.x, ag[q]);
                        ao[q] = ffma2(a, wgo.y, ao[q]);
                    }
                }
            }
            // activations L0
            #pragma unroll
            for (int q = 0; q < BPW; q++) {
                float2 ui = upk2(ai[q]), uf = upk2(af[q]), ug = upk2(ag[q]), uo = upk2(ao[q]);
                float gi = sigap(ui.x + ui.y);
                float gf = sigap(uf.x + uf.y);
                float gg = tanhap(ug.x + ug.y);
                float go = sigap(uo.x + uo.y);
                c0[q] = gf * c0[q] + gi * gg;
                h0wr[q*32 + j] = go * tanhap(c0[q]);
            }
            __syncwarp();    // single per-step barrier

            // ===== Layer 1 =====
            #pragma unroll
            for (int q = 0; q < BPW; q++) {
                ai[q] = pk2(bi1, 0.f); af[q] = pk2(bf1, 0.f);
                ag[q] = pk2(bg1, 0.f); ao[q] = pk2(bo1, 0.f);
            }

            #pragma unroll
            for (int m = 0; m < 8; m++) {
                ulonglong2 h[BPW];
                #pragma unroll
                for (int q = 0; q < BPW; q++)
                    h[q] = ((const ulonglong2*)(h0wr + q*32))[m];
                #pragma unroll
                for (int s = 0; s < 2; s++) {
                    int kp = 2*m + s;
                    ulonglong2 wif = Wih1if[kp*32 + j];
                    ulonglong2 wgo = Wih1go[kp*32 + j];
                    #pragma unroll
                    for (int q = 0; q < BPW; q++) {
                        unsigned long long a = s ? h[q].y : h[q].x;
                        ai[q] = ffma2(a, wif.x, ai[q]);
                        af[q] = ffma2(a, wif.y, af[q]);
                        ag[q] = ffma2(a, wgo.x, ag[q]);
                        ao[q] = ffma2(a, wgo.y, ao[q]);
                    }
                }
            }
            #pragma unroll
            for (int m = 0; m < 8; m++) {
                ulonglong2 h[BPW];
                #pragma unroll
                for (int q = 0; q < BPW; q++)
                    h[q] = ((const ulonglong2*)(h1rd + q*32))[m];
                #pragma unroll
                for (int s = 0; s < 2; s++) {
                    int kp = 2*m + s;
                    ulonglong2 wif = Whh1if[kp*32 + j];
                    ulonglong2 wgo = Whh1go[kp*32 + j];
                    #pragma unroll
                    for (int q = 0; q < BPW; q++) {
                        unsigned long long a = s ? h[q].y : h[q].x;
                        ai[q] = ffma2(a, wif.x, ai[q]);
                        af[q] = ffma2(a, wif.y, af[q]);
                        ag[q] = ffma2(a, wgo.x, ag[q]);
                        ao[q] = ffma2(a, wgo.y, ao[q]);
                    }
                }
            }
            #pragma unroll
            for (int q = 0; q < BPW; q++) {
                float2 ui = upk2(ai[q]), uf = upk2(af[q]), ug = upk2(ag[q]), uo = upk2(ao[q]);
                float gi = sigap(ui.x + ui.y);
                float gf = sigap(uf.x + uf.y);
                float gg = tanhap(ug.x + ug.y);
                float go = sigap(uo.x + uo.y);
                c1[q] = gf * c1[q] + gi * gg;
                float hn = go * tanhap(c1[q]);
                h1wr[q*32 + j] = hn;
                h1last[q] = hn;
            }
            // next step's post-L0 barrier orders h1 stores
        }
        buf ^= 1;
    }

    // ===== final LayerNorm over H=32 =====
    float g = ln_gamma[j];
    float be = ln_beta[j];
    #pragma unroll
    for (int q = 0; q < BPW; q++) {
        if (b0 + q >= BATCH) break;
        float v = h1last[q];
        float s = v;
        #pragma unroll
        for (int o2 = 16; o2 > 0; o2 >>= 1) s += __shfl_xor_sync(0xffffffffu, s, o2);
        float mu = s * (1.0f / 32.0f);
        float dv = v - mu;
        float qq = dv * dv;
        #pragma unroll
        for (int o2 = 16; o2 > 0; o2 >>= 1) qq += __shfl_xor_sync(0xffffffffu, qq, o2);
        float var = qq * (1.0f / 32.0f);
        out[(size_t)(b0 + q) * 32 + j] = dv * rsqrtf(var + 1e-5f) * g + be;
    }
}

extern "C" void kernel_launch(void* const* d_in, const int* in_sizes, int n_in,
                              void* d_out, int out_size)
{
    const float* x      = (const float*)d_in[0];
    const float* W_ih0  = (const float*)d_in[1];
    const float* W_hh0  = (const float*)d_in[2];
    const float* b_ih0  = (const float*)d_in[3];
    const float* b_hh0  = (const float*)d_in[4];
    const float* W_ih1  = (const float*)d_in[5];
    const float* W_hh1  = (const float*)d_in[6];
    const float* b_ih1  = (const float*)d_in[7];
    const float* b_hh1  = (const float*)d_in[8];
    const float* ln_g   = (const float*)d_in[9];
    const float* ln_b   = (const float*)d_in[10];
    float* out = (float*)d_out;

    cudaFuncSetAttribute(lstm_enc_kernel,
                         cudaFuncAttributeMaxDynamicSharedMemorySize, SMEM_BYTES);
    lstm_enc_kernel<<<NUM_CTAS, CTA_THREADS, SMEM_BYTES>>>(
        x, W_ih0, W_hh0, b_ih0, b_hh0, W_ih1, W_hh1, b_ih1, b_hh1,
        ln_g, ln_b, out);
}